// round 15
// baseline (speedup 1.0000x reference)
#include <cuda_runtime.h>
#include <cuda_fp16.h>
#include <math.h>
#include <stdint.h>

#define NN 131072

// ---------------- static device scratch ----------------
__device__ __half g_xh [(size_t)NN * 128];
__device__ __half g_h1 [(size_t)NN * 256];
__device__ __half g_h2 [(size_t)NN * 256];
__device__ __half g_w1f[384 * 128], g_w1b[384 * 128];   // permuted layout (8-block)
__device__ __half g_w2f[384 * 256], g_w2b[384 * 256];   // permuted layout (8-block)
__device__ float  g_wbig[256 * 10];
__device__ float  g_bvec[10];
__device__ float  g_bc[10];

// ---------------- PTX helpers ----------------
__device__ __forceinline__ uint32_t smem_u32(const void* p) {
    uint32_t a;
    asm("{ .reg .u64 t; cvta.to.shared.u64 t, %1; cvt.u32.u64 %0, t; }" : "=r"(a) : "l"(p));
    return a;
}
__device__ __forceinline__ void cp16(uint32_t dst, const void* src) {
    asm volatile("cp.async.cg.shared.global [%0], [%1], 16;" :: "r"(dst), "l"(src));
}
__device__ __forceinline__ void cp_commit() {
    asm volatile("cp.async.commit_group;");
}
__device__ __forceinline__ void cp_wait2() {
    asm volatile("cp.async.wait_group 2;");
}
__device__ __forceinline__ void ldm_x4(uint32_t& r0, uint32_t& r1, uint32_t& r2, uint32_t& r3,
                                       uint32_t addr) {
    asm volatile("ldmatrix.sync.aligned.m8n8.x4.shared.b16 {%0,%1,%2,%3}, [%4];"
                 : "=r"(r0), "=r"(r1), "=r"(r2), "=r"(r3) : "r"(addr));
}
__device__ __forceinline__ void mma_f16(float* d, const uint32_t* a, const uint32_t* b) {
    asm volatile("mma.sync.aligned.m16n8k16.row.col.f32.f16.f16.f32 "
                 "{%0,%1,%2,%3}, {%4,%5,%6,%7}, {%8,%9}, {%0,%1,%2,%3};"
                 : "+f"(d[0]), "+f"(d[1]), "+f"(d[2]), "+f"(d[3])
                 : "r"(a[0]), "r"(a[1]), "r"(a[2]), "r"(a[3]), "r"(b[0]), "r"(b[1]));
}
__device__ __forceinline__ float sigmoidf_(float x) { return 1.f / (1.f + expf(-x)); }

// ================= fused GRU GEMM + gates (16 warps, 48-reg acc, no-spill) =================
// A [NN,K] fp16 K-major. Wp [384,K] fp16 in PERMUTED row order (8-block):
//   orig row g*128+h  ->  new row (h>>3)*24 + g*8 + (h&7)
//   (24 consecutive rows = {r,z,n} x one hidden 8-block)
// CTA: 256 rows x 96 cols (4 hidden 8-blocks x {r,z,n} = one hidden 32-chunk).
// grid.y: dir = y>>2, quarter qq = y&3 (B rows [qq*96, qq*96+96), hidden cols [qq*32,+32)).
// 512 threads / 16 warps: wy = wid&7 (32 rows), wx = wid>>3 (48 cols = 2 gate triples).
__global__ void __launch_bounds__(512, 1)
gru_fused(const __half* __restrict__ A, int K,
          const __half* __restrict__ Wp0, const __half* __restrict__ Wp1,
          const float* __restrict__ bihf, const float* __restrict__ bihb,
          const float* __restrict__ bhhf, const float* __restrict__ bhhb,
          __half* __restrict__ H)
{
    extern __shared__ char sm[];
    constexpr int AST = 80;
    constexpr int ABYTES = 256 * AST;          // 20480
    constexpr int BBYTES = 96 * AST;           // 7680
    constexpr int STAGE = ABYTES + BBYTES;     // 28160
    constexpr int BIAS_OFF = 4 * STAGE;        // 112640

    const int tid = threadIdx.x, lane = tid & 31, wid = tid >> 5;
    const int wy = wid & 7, wx = wid >> 3;
    const int mBase = blockIdx.x * 256;
    const int dir = blockIdx.y >> 2;
    const int qq = blockIdx.y & 3;             // hidden 32-chunk index
    const __half* Wp = dir ? Wp1 : Wp0;
    const float* bih = dir ? bihb : bihf;
    const float* bhh = dir ? bhhb : bhhf;
    const int rowB = qq * 96;
    const int NCH = K >> 5;

    const uint32_t sbase = smem_u32(sm);
    float* s_bih = (float*)(sm + BIAS_OFF);
    float* s_bhh = s_bih + 384;
    for (int i = tid; i < 384; i += 512) { s_bih[i] = bih[i]; s_bhh[i] = bhh[i]; }

    // ---- precomputed copy addressing (per-thread) ----
    const __half* gA0 = A + (size_t)(mBase + (tid >> 2)) * K + (tid & 3) * 8;
    const __half* gA1 = gA0 + (size_t)128 * K;
    const __half* gB0 = Wp + (size_t)(rowB + (tid >> 2)) * K + (tid & 3) * 8;   // tid<384 only
    const uint32_t sA0 = sbase + (tid >> 2) * AST + (tid & 3) * 16;
    const uint32_t sA1 = sA0 + 128 * AST;
    const uint32_t sB0 = sbase + ABYTES + (tid >> 2) * AST + (tid & 3) * 16;

    auto issue = [&](int c) {
        const int kk = c * 32;
        const uint32_t stg = (c & 3) * STAGE;
        cp16(sA0 + stg, gA0 + kk);
        cp16(sA1 + stg, gA1 + kk);
        if (tid < 384) cp16(sB0 + stg, gB0 + kk);
        cp_commit();
    };

    float acc[2][6][4];
#pragma unroll
    for (int i = 0; i < 2; i++)
#pragma unroll
        for (int t = 0; t < 6; t++)
#pragma unroll
            for (int q = 0; q < 4; q++) acc[i][t][q] = 0.f;

    issue(0); issue(1); issue(2);

    const uint32_t a_lrow = lane & 15, a_khalf = (lane >> 4) * 16;
    const uint32_t baseA = sbase + (wy * 32 + a_lrow) * AST + a_khalf;
    const uint32_t baseB = sbase + ABYTES + (wx * 48 + a_lrow) * AST + a_khalf;

    uint32_t stg = 0;
    for (int c = 0; c < NCH; c++) {
        cp_wait2();
        __syncthreads();
        if (c + 3 < NCH) issue(c + 3);
        else cp_commit();            // keep group count aligned (tail-race fix)
        const uint32_t bA = baseA + stg;
        const uint32_t bB = baseB + stg;
#pragma unroll
        for (int kh = 0; kh < 2; kh++) {
            uint32_t a[2][4];
#pragma unroll
            for (int i = 0; i < 2; i++)
                ldm_x4(a[i][0], a[i][1], a[i][2], a[i][3],
                       bA + i * (16 * AST) + kh * 32);
            uint32_t bf[6][2];
#pragma unroll
            for (int jj = 0; jj < 3; jj++) {
                uint32_t r0, r1, r2, r3;
                ldm_x4(r0, r1, r2, r3,
                       bB + jj * (16 * AST) + kh * 32);
                bf[2 * jj][0] = r0; bf[2 * jj][1] = r2;
                bf[2 * jj + 1][0] = r1; bf[2 * jj + 1][1] = r3;
            }
#pragma unroll
            for (int i = 0; i < 2; i++)
#pragma unroll
                for (int t = 0; t < 6; t++)
                    mma_f16(acc[i][t], a[i], bf[t]);
        }
        stg = (stg == 3 * STAGE) ? 0u : stg + STAGE;
    }

    // ---- fused gate epilogue ----
    // Warp covers B rows [qq*96 + wx*48, +48) = hidden 8-blocks {qq*4+wx*2, +1};
    // tile t = 3*b + g (b = block-within-warp, g = gate r/z/n).
#pragma unroll
    for (int i = 0; i < 2; i++) {
#pragma unroll
        for (int b = 0; b < 2; b++) {
            int hblock = qq * 4 + wx * 2 + b;
#pragma unroll
            for (int rp = 0; rp < 2; rp++) {
                int row = mBase + wy * 32 + i * 16 + (lane >> 2) + rp * 8;
                __half hv[2];
#pragma unroll
                for (int q = 0; q < 2; q++) {
                    int h = hblock * 8 + (lane & 3) * 2 + q;
                    float ir = acc[i][3 * b + 0][rp * 2 + q];
                    float iz = acc[i][3 * b + 1][rp * 2 + q];
                    float in = acc[i][3 * b + 2][rp * 2 + q];
                    float r  = sigmoidf_(ir + s_bih[h] + s_bhh[h]);
                    float z  = sigmoidf_(iz + s_bih[128 + h] + s_bhh[128 + h]);
                    float ng = tanhf(in + s_bih[256 + h] + r * s_bhh[256 + h]);
                    hv[q] = __float2half_rn((1.f - z) * ng);
                }
                *(__half2*)(H + (size_t)row * 256 + dir * 128 + hblock * 8 + (lane & 3) * 2) =
                    *(__half2*)hv;
            }
        }
    }
}

// ---------------- prep kernels ----------------
__global__ void cvt_h(const float* __restrict__ src, __half* __restrict__ dst, size_t n) {
    size_t i = (size_t)blockIdx.x * blockDim.x + threadIdx.x;
    if (i < n) dst[i] = __float2half_rn(src[i]);
}

// permuted GRU weight for all 4 weight matrices in one launch (8-block layout):
// orig row g*128+h -> new row (h>>3)*24 + g*8 + (h&7)
__global__ void w_prep_all(const float* __restrict__ w0, const float* __restrict__ w1,
                           const float* __restrict__ w2, const float* __restrict__ w3,
                           __half* __restrict__ p0, __half* __restrict__ p1,
                           __half* __restrict__ p2, __half* __restrict__ p3)
{
    int which = blockIdx.y;
    const float* w = which == 0 ? w0 : which == 1 ? w1 : which == 2 ? w2 : w3;
    __half* wp      = which == 0 ? p0 : which == 1 ? p1 : which == 2 ? p2 : p3;
    int K = (which < 2) ? 128 : 256;
    int i = blockIdx.x * blockDim.x + threadIdx.x;
    if (i >= 384 * K) return;
    int p = i / K, k = i - p * K;
    int g = p >> 7, h = p & 127;
    int nr = (h >> 3) * 24 + g * 8 + (h & 7);
    wp[(size_t)nr * K + k] = __float2half_rn(w[i]);
}

// Wbig = Wg1 @ (Wg2 @ Wfc)  [256,10];  bvec = bg1 @ (Wg2@Wfc);  bc = bg2@Wfc + bfc
__global__ void wbig_prep(const float* __restrict__ wg1, const float* __restrict__ bg1,
                          const float* __restrict__ wg2, const float* __restrict__ bg2,
                          const float* __restrict__ wfc, const float* __restrict__ bfc,
                          float* __restrict__ Wbig, float* __restrict__ bvec,
                          float* __restrict__ bc)
{
    __shared__ float t1[1280];            // [128,10] = wg2 @ wfc
    int tid = threadIdx.x;
    for (int i = tid; i < 1280; i += 256) {
        int j = i / 10, c = i - j * 10;
        float s = 0.f;
        for (int m = 0; m < 64; m++) s += wg2[j * 64 + m] * wfc[m * 10 + c];
        t1[i] = s;
    }
    __syncthreads();
    for (int i = tid; i < 2560; i += 256) {
        int j = i / 10, c = i - j * 10;
        float s = 0.f;
        for (int k = 0; k < 128; k++) s += wg1[j * 128 + k] * t1[k * 10 + c];
        Wbig[i] = s;
    }
    if (tid < 10) {
        float s = 0.f;
        for (int k = 0; k < 128; k++) s += bg1[k] * t1[k * 10 + tid];
        bvec[tid] = s;
        float s2 = 0.f;
        for (int m = 0; m < 64; m++) s2 += bg2[m] * wfc[m * 10 + tid];
        bc[tid] = s2 + bfc[tid];
    }
}

// ================= fused S^2 stencil + final projection =================
__global__ void __launch_bounds__(256)
fc_final(const __half* __restrict__ h2, const float* __restrict__ Wbig,
         const float* __restrict__ bvec, const float* __restrict__ bc,
         float* __restrict__ out, int n)
{
    __shared__ float sW[2560];
    __shared__ float sbv[10], sbc[10];
    int tid = threadIdx.x;
    for (int i = tid; i < 2560; i += 256) sW[i] = Wbig[i];
    if (tid < 10) { sbv[tid] = bvec[tid]; sbc[tid] = bc[tid]; }
    __syncthreads();

    int i = blockIdx.x * 256 + tid;
    if (i >= n) return;

    auto dfun = [n](int j) -> float {
        if (j < 0 || j >= n) return 0.f;
        return rsqrtf(1.f + (float)(j > 0) + (float)(j < n - 1));
    };
    float dm2 = dfun(i - 2), dm1 = dfun(i - 1), d0 = dfun(i);
    float dp1 = dfun(i + 1), dp2 = dfun(i + 2);
    float w0 = d0 * dm2 * dm1 * dm1;
    float w1 = d0 * dm1 * (dm1 * dm1 + d0 * d0);
    float w2 = d0 * d0 * (dm1 * dm1 + d0 * d0 + dp1 * dp1);
    float w3 = d0 * dp1 * (dp1 * dp1 + d0 * d0);
    float w4 = d0 * dp2 * dp1 * dp1;
    float si = d0 * (dm1 + d0 + dp1);

    float acc[10];
#pragma unroll
    for (int c = 0; c < 10; c++) acc[c] = si * sbv[c] + sbc[c];

    int j0 = max(i - 2, 0), j1 = max(i - 1, 0);
    int j3 = min(i + 1, n - 1), j4 = min(i + 2, n - 1);
    const uint4* r0 = (const uint4*)(h2 + (size_t)j0 * 256);
    const uint4* r1 = (const uint4*)(h2 + (size_t)j1 * 256);
    const uint4* r2 = (const uint4*)(h2 + (size_t)i  * 256);
    const uint4* r3 = (const uint4*)(h2 + (size_t)j3 * 256);
    const uint4* r4 = (const uint4*)(h2 + (size_t)j4 * 256);

    for (int kb = 0; kb < 32; kb++) {
        uint4 q0 = r0[kb], q1 = r1[kb], q2 = r2[kb], q3 = r3[kb], q4 = r4[kb];
#pragma unroll
        for (int u = 0; u < 4; u++) {
            float2 f0 = __half22float2(((const __half2*)&q0)[u]);
            float2 f1 = __half22float2(((const __half2*)&q1)[u]);
            float2 f2 = __half22float2(((const __half2*)&q2)[u]);
            float2 f3 = __half22float2(((const __half2*)&q3)[u]);
            float2 f4 = __half22float2(((const __half2*)&q4)[u]);
            float zx = w0 * f0.x + w1 * f1.x + w2 * f2.x + w3 * f3.x + w4 * f4.x;
            float zy = w0 * f0.y + w1 * f1.y + w2 * f2.y + w3 * f3.y + w4 * f4.y;
            int kcol = kb * 8 + u * 2;
            const float* wA = &sW[kcol * 10];
            const float* wB = &sW[(kcol + 1) * 10];
#pragma unroll
            for (int c = 0; c < 10; c++)
                acc[c] += zx * wA[c] + zy * wB[c];
        }
    }
#pragma unroll
    for (int c = 0; c < 10; c++)
        out[(size_t)i * 10 + c] = acc[c];
}

// ---------------- launch ----------------
extern "C" void kernel_launch(void* const* d_in, const int* in_sizes, int n_in,
                              void* d_out, int out_size)
{
    const float* x       = (const float*)d_in[0];
    const float* w_ih_f1 = (const float*)d_in[1];
    const float* b_ih_f1 = (const float*)d_in[2];
    const float* b_hh_f1 = (const float*)d_in[3];
    const float* w_ih_b1 = (const float*)d_in[4];
    const float* b_ih_b1 = (const float*)d_in[5];
    const float* b_hh_b1 = (const float*)d_in[6];
    const float* w_ih_f2 = (const float*)d_in[7];
    const float* b_ih_f2 = (const float*)d_in[8];
    const float* b_hh_f2 = (const float*)d_in[9];
    const float* w_ih_b2 = (const float*)d_in[10];
    const float* b_ih_b2 = (const float*)d_in[11];
    const float* b_hh_b2 = (const float*)d_in[12];
    const float* w_g1    = (const float*)d_in[13];
    const float* b_g1    = (const float*)d_in[14];
    const float* w_g2    = (const float*)d_in[15];
    const float* b_g2    = (const float*)d_in[16];
    const float* w_fc    = (const float*)d_in[17];
    const float* b_fc    = (const float*)d_in[18];
    float* out = (float*)d_out;

    __half *xh, *h1, *h2, *w1f, *w1b, *w2f, *w2b;
    float *wbig, *bvec, *bc;
    cudaGetSymbolAddress((void**)&xh, g_xh);
    cudaGetSymbolAddress((void**)&h1, g_h1);
    cudaGetSymbolAddress((void**)&h2, g_h2);
    cudaGetSymbolAddress((void**)&w1f, g_w1f); cudaGetSymbolAddress((void**)&w1b, g_w1b);
    cudaGetSymbolAddress((void**)&w2f, g_w2f); cudaGetSymbolAddress((void**)&w2b, g_w2b);
    cudaGetSymbolAddress((void**)&wbig, g_wbig);
    cudaGetSymbolAddress((void**)&bvec, g_bvec);
    cudaGetSymbolAddress((void**)&bc, g_bc);

    const int GRU_SMEM = 4 * 28160 + 2 * 384 * 4;    // 115712
    cudaFuncSetAttribute(gru_fused, cudaFuncAttributeMaxDynamicSharedMemorySize, GRU_SMEM);

    dim3 blk(256);

    // prep
    cvt_h<<<((size_t)NN * 128 + 255) / 256, blk>>>(x, xh, (size_t)NN * 128);
    w_prep_all<<<dim3((384 * 256 + 255) / 256, 4), blk>>>(
        w_ih_f1, w_ih_b1, w_ih_f2, w_ih_b2, w1f, w1b, w2f, w2b);
    wbig_prep<<<1, blk>>>(w_g1, b_g1, w_g2, b_g2, w_fc, b_fc, wbig, bvec, bc);

    // GRU layer 1 (K=128): fused GEMM+gates -> h1 fp16
    gru_fused<<<dim3(NN / 256, 8), 512, GRU_SMEM>>>(
        xh, 128, w1f, w1b, b_ih_f1, b_ih_b1, b_hh_f1, b_hh_b1, h1);

    // GRU layer 2 (K=256): -> h2 fp16
    gru_fused<<<dim3(NN / 256, 8), 512, GRU_SMEM>>>(
        h1, 256, w2f, w2b, b_ih_f2, b_ih_b2, b_hh_f2, b_hh_b2, h2);

    // fused S^2 stencil + (GCN1·GCN2·fc) collapsed projection
    fc_final<<<NN / 256, blk>>>(h2, wbig, bvec, bc, out, NN);
}

// round 16
// speedup vs baseline: 1.1238x; 1.1238x over previous
#include <cuda_runtime.h>
#include <cuda_fp16.h>
#include <math.h>
#include <stdint.h>

#define NN 131072

// ---------------- static device scratch ----------------
__device__ __half g_xh [(size_t)NN * 128];
__device__ __half g_h1 [(size_t)NN * 256];
__device__ __half g_h2 [(size_t)NN * 256];
__device__ __half g_w1f[384 * 128], g_w1b[384 * 128];   // permuted layout (32-block)
__device__ __half g_w2f[384 * 256], g_w2b[384 * 256];   // permuted layout (32-block)
__device__ float  g_wbig[256 * 10];
__device__ float  g_bvec[10];
__device__ float  g_bc[10];

// ---------------- PTX helpers ----------------
__device__ __forceinline__ uint32_t smem_u32(const void* p) {
    uint32_t a;
    asm("{ .reg .u64 t; cvta.to.shared.u64 t, %1; cvt.u32.u64 %0, t; }" : "=r"(a) : "l"(p));
    return a;
}
__device__ __forceinline__ void cp16(uint32_t dst, const void* src) {
    asm volatile("cp.async.cg.shared.global [%0], [%1], 16;" :: "r"(dst), "l"(src));
}
__device__ __forceinline__ void cp_commit() {
    asm volatile("cp.async.commit_group;");
}
__device__ __forceinline__ void cp_wait2() {
    asm volatile("cp.async.wait_group 2;");
}
__device__ __forceinline__ void ldm_x4(uint32_t& r0, uint32_t& r1, uint32_t& r2, uint32_t& r3,
                                       uint32_t addr) {
    asm volatile("ldmatrix.sync.aligned.m8n8.x4.shared.b16 {%0,%1,%2,%3}, [%4];"
                 : "=r"(r0), "=r"(r1), "=r"(r2), "=r"(r3) : "r"(addr));
}
__device__ __forceinline__ void mma_f16(float* d, const uint32_t* a, const uint32_t* b) {
    asm volatile("mma.sync.aligned.m16n8k16.row.col.f32.f16.f16.f32 "
                 "{%0,%1,%2,%3}, {%4,%5,%6,%7}, {%8,%9}, {%0,%1,%2,%3};"
                 : "+f"(d[0]), "+f"(d[1]), "+f"(d[2]), "+f"(d[3])
                 : "r"(a[0]), "r"(a[1]), "r"(a[2]), "r"(a[3]), "r"(b[0]), "r"(b[1]));
}
__device__ __forceinline__ float sigmoidf_(float x) { return 1.f / (1.f + expf(-x)); }

// ================= fused GRU GEMM + gates (R13 optimum: 16 warps, 48 MMA/warp/sync) =================
// A [NN,K] fp16 K-major. Wp [384,K] fp16 in PERMUTED row order:
//   orig row g*128+h  ->  new row (h>>5)*96 + g*32 + (h&31)
// CTA: 256 rows x 192 cols (2 hidden 32-blocks x {r,z,n}).
// grid.y: dir = y>>1, hb = y&1 (B row base hb*192).
// 512 threads / 16 warps: wy=wid&7 (32 rows each), wx=wid>>3 (96 cols each).
// Mainloop consumes B in TWO halves per kh-step to halve live B fragments.
__global__ void __launch_bounds__(512, 1)
gru_fused(const __half* __restrict__ A, int K,
          const __half* __restrict__ Wp0, const __half* __restrict__ Wp1,
          const float* __restrict__ bihf, const float* __restrict__ bihb,
          const float* __restrict__ bhhf, const float* __restrict__ bhhb,
          __half* __restrict__ H)
{
    extern __shared__ char sm[];
    constexpr int AST = 80;
    constexpr int ABYTES = 256 * AST;          // 20480
    constexpr int BBYTES = 192 * AST;          // 15360
    constexpr int STAGE = ABYTES + BBYTES;     // 35840
    constexpr int BIAS_OFF = 4 * STAGE;        // 143360

    const int tid = threadIdx.x, lane = tid & 31, wid = tid >> 5;
    const int wy = wid & 7, wx = wid >> 3;
    const int mBase = blockIdx.x * 256;
    const int dir = blockIdx.y >> 1;
    const int hb = blockIdx.y & 1;
    const __half* Wp = dir ? Wp1 : Wp0;
    const float* bih = dir ? bihb : bihf;
    const float* bhh = dir ? bhhb : bhhf;
    const int rowB = hb * 192;
    const int NCH = K >> 5;

    const uint32_t sbase = smem_u32(sm);
    float* s_bih = (float*)(sm + BIAS_OFF);
    float* s_bhh = s_bih + 384;
    for (int i = tid; i < 384; i += 512) { s_bih[i] = bih[i]; s_bhh[i] = bhh[i]; }

    auto issue = [&](int c) {
        int kk = c * 32;
        uint32_t st = sbase + (c & 3) * STAGE;
        // A: 256 rows x 4 x 16B = 1024 units (2 per thread)
#pragma unroll
        for (int it = 0; it < 2; it++) {
            int u = tid + it * 512;
            cp16(st + (u >> 2) * AST + (u & 3) * 16,
                 A + (size_t)(mBase + (u >> 2)) * K + kk + (u & 3) * 8);
        }
        // B: 192 rows x 4 = 768 units
        {
            int u = tid;
            cp16(st + ABYTES + (u >> 2) * AST + (u & 3) * 16,
                 Wp + (size_t)(rowB + (u >> 2)) * K + kk + (u & 3) * 8);
        }
        if (tid < 256) {
            int u = 512 + tid;
            cp16(st + ABYTES + (u >> 2) * AST + (u & 3) * 16,
                 Wp + (size_t)(rowB + (u >> 2)) * K + kk + (u & 3) * 8);
        }
        cp_commit();
    };

    float acc[2][12][4];
#pragma unroll
    for (int i = 0; i < 2; i++)
#pragma unroll
        for (int t = 0; t < 12; t++)
#pragma unroll
            for (int q = 0; q < 4; q++) acc[i][t][q] = 0.f;

    issue(0); issue(1); issue(2);

    const uint32_t a_lrow = lane & 15, a_khalf = (lane >> 4) * 16;
    for (int c = 0; c < NCH; c++) {
        cp_wait2();
        __syncthreads();
        if (c + 3 < NCH) issue(c + 3);
        else cp_commit();            // keep group count aligned (tail-race fix)
        uint32_t st = sbase + (c & 3) * STAGE;
#pragma unroll
        for (int kh = 0; kh < 2; kh++) {
            uint32_t a[2][4];
#pragma unroll
            for (int i = 0; i < 2; i++)
                ldm_x4(a[i][0], a[i][1], a[i][2], a[i][3],
                       st + (wy * 32 + i * 16 + a_lrow) * AST + kh * 32 + a_khalf);
            // consume B in two halves: 3 ldmatrix + 12 MMAs each (halves live frags)
#pragma unroll
            for (int half = 0; half < 2; half++) {
                uint32_t bf[6][2];
#pragma unroll
                for (int jj = 0; jj < 3; jj++) {
                    uint32_t r0, r1, r2, r3;
                    ldm_x4(r0, r1, r2, r3,
                           st + ABYTES + (wx * 96 + (half * 3 + jj) * 16 + a_lrow) * AST
                              + kh * 32 + a_khalf);
                    bf[2 * jj][0] = r0; bf[2 * jj][1] = r2;
                    bf[2 * jj + 1][0] = r1; bf[2 * jj + 1][1] = r3;
                }
#pragma unroll
                for (int i = 0; i < 2; i++)
#pragma unroll
                    for (int t = 0; t < 6; t++)
                        mma_f16(acc[i][half * 6 + t], a[i], bf[t]);
            }
        }
    }

    // ---- fused gate epilogue ----
    const int s = hb * 2 + wx;                 // hidden 32-block index (0..3)
#pragma unroll
    for (int i = 0; i < 2; i++) {
#pragma unroll
        for (int t = 0; t < 4; t++) {
#pragma unroll
            for (int rp = 0; rp < 2; rp++) {
                int row = mBase + wy * 32 + i * 16 + (lane >> 2) + rp * 8;
                __half hv[2];
#pragma unroll
                for (int q = 0; q < 2; q++) {
                    int h = s * 32 + t * 8 + (lane & 3) * 2 + q;
                    float ir = acc[i][t][rp * 2 + q];
                    float iz = acc[i][t + 4][rp * 2 + q];
                    float in = acc[i][t + 8][rp * 2 + q];
                    float r  = sigmoidf_(ir + s_bih[h] + s_bhh[h]);
                    float z  = sigmoidf_(iz + s_bih[128 + h] + s_bhh[128 + h]);
                    float ng = tanhf(in + s_bih[256 + h] + r * s_bhh[256 + h]);
                    hv[q] = __float2half_rn((1.f - z) * ng);
                }
                *(__half2*)(H + (size_t)row * 256 + dir * 128 + s * 32 + t * 8 + (lane & 3) * 2) =
                    *(__half2*)hv;
            }
        }
    }
}

// ---------------- prep kernels ----------------
__global__ void cvt_h(const float* __restrict__ src, __half* __restrict__ dst, size_t n) {
    size_t i = (size_t)blockIdx.x * blockDim.x + threadIdx.x;
    if (i < n) dst[i] = __float2half_rn(src[i]);
}

// permuted GRU weight for all 4 weight matrices in one launch.
__global__ void w_prep_all(const float* __restrict__ w0, const float* __restrict__ w1,
                           const float* __restrict__ w2, const float* __restrict__ w3,
                           __half* __restrict__ p0, __half* __restrict__ p1,
                           __half* __restrict__ p2, __half* __restrict__ p3)
{
    int which = blockIdx.y;
    const float* w = which == 0 ? w0 : which == 1 ? w1 : which == 2 ? w2 : w3;
    __half* wp      = which == 0 ? p0 : which == 1 ? p1 : which == 2 ? p2 : p3;
    int K = (which < 2) ? 128 : 256;
    int i = blockIdx.x * blockDim.x + threadIdx.x;
    if (i >= 384 * K) return;
    int p = i / K, k = i - p * K;
    int g = p >> 7, h = p & 127;
    int nr = (h >> 5) * 96 + g * 32 + (h & 31);
    wp[(size_t)nr * K + k] = __float2half_rn(w[i]);
}

// Wbig = Wg1 @ (Wg2 @ Wfc)  [256,10];  bvec = bg1 @ (Wg2@Wfc);  bc = bg2@Wfc + bfc
__global__ void wbig_prep(const float* __restrict__ wg1, const float* __restrict__ bg1,
                          const float* __restrict__ wg2, const float* __restrict__ bg2,
                          const float* __restrict__ wfc, const float* __restrict__ bfc,
                          float* __restrict__ Wbig, float* __restrict__ bvec,
                          float* __restrict__ bc)
{
    __shared__ float t1[1280];            // [128,10] = wg2 @ wfc
    int tid = threadIdx.x;
    for (int i = tid; i < 1280; i += 256) {
        int j = i / 10, c = i - j * 10;
        float s = 0.f;
        for (int m = 0; m < 64; m++) s += wg2[j * 64 + m] * wfc[m * 10 + c];
        t1[i] = s;
    }
    __syncthreads();
    for (int i = tid; i < 2560; i += 256) {
        int j = i / 10, c = i - j * 10;
        float s = 0.f;
        for (int k = 0; k < 128; k++) s += wg1[j * 128 + k] * t1[k * 10 + c];
        Wbig[i] = s;
    }
    if (tid < 10) {
        float s = 0.f;
        for (int k = 0; k < 128; k++) s += bg1[k] * t1[k * 10 + tid];
        bvec[tid] = s;
        float s2 = 0.f;
        for (int m = 0; m < 64; m++) s2 += bg2[m] * wfc[m * 10 + tid];
        bc[tid] = s2 + bfc[tid];
    }
}

// ================= fused S^2 stencil + final projection =================
__global__ void __launch_bounds__(256)
fc_final(const __half* __restrict__ h2, const float* __restrict__ Wbig,
         const float* __restrict__ bvec, const float* __restrict__ bc,
         float* __restrict__ out, int n)
{
    __shared__ float sW[2560];
    __shared__ float sbv[10], sbc[10];
    int tid = threadIdx.x;
    for (int i = tid; i < 2560; i += 256) sW[i] = Wbig[i];
    if (tid < 10) { sbv[tid] = bvec[tid]; sbc[tid] = bc[tid]; }
    __syncthreads();

    int i = blockIdx.x * 256 + tid;
    if (i >= n) return;

    auto dfun = [n](int j) -> float {
        if (j < 0 || j >= n) return 0.f;
        return rsqrtf(1.f + (float)(j > 0) + (float)(j < n - 1));
    };
    float dm2 = dfun(i - 2), dm1 = dfun(i - 1), d0 = dfun(i);
    float dp1 = dfun(i + 1), dp2 = dfun(i + 2);
    float w0 = d0 * dm2 * dm1 * dm1;
    float w1 = d0 * dm1 * (dm1 * dm1 + d0 * d0);
    float w2 = d0 * d0 * (dm1 * dm1 + d0 * d0 + dp1 * dp1);
    float w3 = d0 * dp1 * (dp1 * dp1 + d0 * d0);
    float w4 = d0 * dp2 * dp1 * dp1;
    float si = d0 * (dm1 + d0 + dp1);

    float acc[10];
#pragma unroll
    for (int c = 0; c < 10; c++) acc[c] = si * sbv[c] + sbc[c];

    int j0 = max(i - 2, 0), j1 = max(i - 1, 0);
    int j3 = min(i + 1, n - 1), j4 = min(i + 2, n - 1);
    const uint4* r0 = (const uint4*)(h2 + (size_t)j0 * 256);
    const uint4* r1 = (const uint4*)(h2 + (size_t)j1 * 256);
    const uint4* r2 = (const uint4*)(h2 + (size_t)i  * 256);
    const uint4* r3 = (const uint4*)(h2 + (size_t)j3 * 256);
    const uint4* r4 = (const uint4*)(h2 + (size_t)j4 * 256);

    for (int kb = 0; kb < 32; kb++) {
        uint4 q0 = r0[kb], q1 = r1[kb], q2 = r2[kb], q3 = r3[kb], q4 = r4[kb];
#pragma unroll
        for (int u = 0; u < 4; u++) {
            float2 f0 = __half22float2(((const __half2*)&q0)[u]);
            float2 f1 = __half22float2(((const __half2*)&q1)[u]);
            float2 f2 = __half22float2(((const __half2*)&q2)[u]);
            float2 f3 = __half22float2(((const __half2*)&q3)[u]);
            float2 f4 = __half22float2(((const __half2*)&q4)[u]);
            float zx = w0 * f0.x + w1 * f1.x + w2 * f2.x + w3 * f3.x + w4 * f4.x;
            float zy = w0 * f0.y + w1 * f1.y + w2 * f2.y + w3 * f3.y + w4 * f4.y;
            int kcol = kb * 8 + u * 2;
            const float* wA = &sW[kcol * 10];
            const float* wB = &sW[(kcol + 1) * 10];
#pragma unroll
            for (int c = 0; c < 10; c++)
                acc[c] += zx * wA[c] + zy * wB[c];
        }
    }
#pragma unroll
    for (int c = 0; c < 10; c++)
        out[(size_t)i * 10 + c] = acc[c];
}

// ---------------- launch ----------------
extern "C" void kernel_launch(void* const* d_in, const int* in_sizes, int n_in,
                              void* d_out, int out_size)
{
    const float* x       = (const float*)d_in[0];
    const float* w_ih_f1 = (const float*)d_in[1];
    const float* b_ih_f1 = (const float*)d_in[2];
    const float* b_hh_f1 = (const float*)d_in[3];
    const float* w_ih_b1 = (const float*)d_in[4];
    const float* b_ih_b1 = (const float*)d_in[5];
    const float* b_hh_b1 = (const float*)d_in[6];
    const float* w_ih_f2 = (const float*)d_in[7];
    const float* b_ih_f2 = (const float*)d_in[8];
    const float* b_hh_f2 = (const float*)d_in[9];
    const float* w_ih_b2 = (const float*)d_in[10];
    const float* b_ih_b2 = (const float*)d_in[11];
    const float* b_hh_b2 = (const float*)d_in[12];
    const float* w_g1    = (const float*)d_in[13];
    const float* b_g1    = (const float*)d_in[14];
    const float* w_g2    = (const float*)d_in[15];
    const float* b_g2    = (const float*)d_in[16];
    const float* w_fc    = (const float*)d_in[17];
    const float* b_fc    = (const float*)d_in[18];
    float* out = (float*)d_out;

    __half *xh, *h1, *h2, *w1f, *w1b, *w2f, *w2b;
    float *wbig, *bvec, *bc;
    cudaGetSymbolAddress((void**)&xh, g_xh);
    cudaGetSymbolAddress((void**)&h1, g_h1);
    cudaGetSymbolAddress((void**)&h2, g_h2);
    cudaGetSymbolAddress((void**)&w1f, g_w1f); cudaGetSymbolAddress((void**)&w1b, g_w1b);
    cudaGetSymbolAddress((void**)&w2f, g_w2f); cudaGetSymbolAddress((void**)&w2b, g_w2b);
    cudaGetSymbolAddress((void**)&wbig, g_wbig);
    cudaGetSymbolAddress((void**)&bvec, g_bvec);
    cudaGetSymbolAddress((void**)&bc, g_bc);

    const int GRU_SMEM = 4 * 35840 + 2 * 384 * 4;    // 146432
    cudaFuncSetAttribute(gru_fused, cudaFuncAttributeMaxDynamicSharedMemorySize, GRU_SMEM);

    dim3 blk(256);

    // prep
    cvt_h<<<((size_t)NN * 128 + 255) / 256, blk>>>(x, xh, (size_t)NN * 128);
    w_prep_all<<<dim3((384 * 256 + 255) / 256, 4), blk>>>(
        w_ih_f1, w_ih_b1, w_ih_f2, w_ih_b2, w1f, w1b, w2f, w2b);
    wbig_prep<<<1, blk>>>(w_g1, b_g1, w_g2, b_g2, w_fc, b_fc, wbig, bvec, bc);

    // GRU layer 1 (K=128): fused GEMM+gates -> h1 fp16
    gru_fused<<<dim3(NN / 256, 4), 512, GRU_SMEM>>>(
        xh, 128, w1f, w1b, b_ih_f1, b_ih_b1, b_hh_f1, b_hh_b1, h1);

    // GRU layer 2 (K=256): -> h2 fp16
    gru_fused<<<dim3(NN / 256, 4), 512, GRU_SMEM>>>(
        h1, 256, w2f, w2b, b_ih_f2, b_ih_b2, b_hh_f2, b_hh_b2, h2);

    // fused S^2 stencil + (GCN1·GCN2·fc) collapsed projection
    fc_final<<<NN / 256, blk>>>(h2, wbig, bvec, bc, out, NN);
}